// round 13
// baseline (speedup 1.0000x reference)
#include <cuda_runtime.h>

#define Bc 4
#define Lc 2048
#define Hc 8
#define Vc 64
#define HVc 512
#define NTHREADS 256

__device__ __forceinline__ float to_tf32(float x) {
    float r; asm("cvt.rna.tf32.f32 %0, %1;" : "=f"(r) : "f"(x)); return r;
}
// D += A(m16k8,row) * B(k8n8,col), tf32
__device__ __forceinline__ void mma8(float* d, const unsigned* a,
                                     unsigned b0, unsigned b1) {
    asm("mma.sync.aligned.m16n8k8.row.col.f32.tf32.tf32.f32 "
        "{%0,%1,%2,%3}, {%4,%5,%6,%7}, {%8,%9}, {%0,%1,%2,%3};"
        : "+f"(d[0]), "+f"(d[1]), "+f"(d[2]), "+f"(d[3])
        : "r"(a[0]), "r"(a[1]), "r"(a[2]), "r"(a[3]), "r"(b0), "r"(b1));
}
__device__ __forceinline__ float ex2(float x) {
    float r; asm("ex2.approx.ftz.f32 %0, %1;" : "=f"(r) : "f"(x)); return r;
}

// ---- persistent device scratch ----
__device__ float g_att[Bc * Lc * HVc];          // normalized attended
__device__ float g_vb[Bc * 256 * 64 * 32 * 2];  // V in b-fragment order (tf32)
__device__ float g_wb[64 * 64 * 32 * 2];        // W in b-fragment order (tf32)
__device__ float g_kpos4[Bc * Lc * 4];          // compacted kpos (x,y,z,|k|^2), pad=1000
__device__ int   g_idx[Bc * Lc];
__device__ int   g_cnt[Bc];

// ================= compaction =================
__global__ void compact_kernel(const int* __restrict__ mask)
{
    const int b = blockIdx.x;
    const int lane = threadIdx.x;
    int cnt = 0;
    for (int k0 = 0; k0 < Lc; k0 += 32) {
        const int k = k0 + lane;
        const bool u = (mask[b * Lc + k] == 0);
        const unsigned bal = __ballot_sync(0xFFFFFFFFu, u);
        if (u) {
            const int pos = cnt + __popc(bal & ((1u << lane) - 1u));
            g_idx[b * Lc + pos] = k;
        }
        cnt += __popc(bal);
    }
    if (lane == 0) g_cnt[b] = cnt;
}

// ====== gather: values -> b-fragment layout (tf32); kpos4 with |k|^2 ======
__global__ void gather_kernel(const float* __restrict__ kpos,
                              const float* __restrict__ values)
{
    const int b  = blockIdx.x >> 5;
    const int j0 = (blockIdx.x & 31) * 64;
    const int tid = threadIdx.x;
    __shared__ int s_idx[64];
    __shared__ int s_n[2];

    if (tid == 0) { int c = g_cnt[b]; s_n[0] = c; s_n[1] = (c + 31) & ~31; }
    if (tid < 64 && j0 + tid < Lc) s_idx[tid] = g_idx[b * Lc + j0 + tid];
    __syncthreads();
    const int cnt = s_n[0];
    const int pad = s_n[1];
    const int jend = min(j0 + 64, pad);
    if (jend <= j0) return;
    const int nrows = jend - j0;

    const float4* v4 = (const float4*)values;
    for (int e = tid; e < nrows * 128; e += NTHREADS) {
        const int jl = e >> 7;
        const int c4 = e & 127;
        const int j  = j0 + jl;
        float4 v;
        if (j < cnt) v = v4[(size_t)(b * Lc + s_idx[jl]) * 128 + c4];
        else         v = make_float4(0.f, 0.f, 0.f, 0.f);
        v.x = to_tf32(v.x); v.y = to_tf32(v.y);
        v.z = to_tf32(v.z); v.w = to_tf32(v.w);
        const int ksg = j >> 3, kk = j & 7;
        const int tc = kk & 3, reg = kk >> 2;
        const float* pv = &v.x;
        #pragma unroll
        for (int t = 0; t < 4; t++) {
            const int c = c4 * 4 + t;
            const int h = c >> 6, n = (c >> 3) & 7, gr = c & 7;
            const size_t idx =
                ((((size_t)b * 256 + ksg) * 64 + h * 8 + n) * 32 + gr * 4 + tc) * 2 + reg;
            g_vb[idx] = pv[t];
        }
    }
    for (int jl = tid; jl < nrows; jl += NTHREADS) {
        const int j = j0 + jl;
        float x, y, z;
        if (j < cnt) {
            const float* p = kpos + (size_t)(b * Lc + s_idx[jl]) * 3;
            x = p[0]; y = p[1]; z = p[2];
        } else {
            x = y = z = 1000.0f;
        }
        const float k2 = x * x + y * y + z * z;
        ((float4*)g_kpos4)[(size_t)b * Lc + j] = make_float4(x, y, z, k2);
    }
}

// ====== W prepack: b-fragment order, tf32 ======
__global__ void prep_w(const float* __restrict__ W)
{
    const int p = blockIdx.x * 256 + threadIdx.x;   // float2 slot
    const int tc = p & 3;
    const int gr = (p >> 2) & 7;
    const int nb = (p >> 5) & 63;
    const int kb = p >> 11;
    const int row = nb * 8 + gr;
    const int col = kb * 8 + tc;
    g_wb[2 * p]     = to_tf32(W[row * HVc + col]);
    g_wb[2 * p + 1] = to_tf32(W[row * HVc + col + 4]);
}

// ====== attend: warp-autonomous + register software pipeline ======
// warp = (b, 32-query tile, head, n-half). 4 n8-tiles per warp (acc 32 regs).
// Depth-1 prefetch: kpos4 + b-frags for step s+1 issued before step s's math.
__global__ __launch_bounds__(128, 4)
void attend_kernel(const float* __restrict__ qpos,
                   const float* __restrict__ ls)
{
    const int lane = threadIdx.x & 31;
    const int warp = threadIdx.x >> 5;
    const int gw = blockIdx.x * 4 + warp;   // 4096 warps total
    const int b  = gw >> 10;
    const int qt = (gw >> 4) & 63;
    const int h  = (gw >> 1) & 7;
    const int nh = gw & 1;
    const int gr = lane >> 2;
    const int tc = lane & 3;

    const float l = ls[h];
    const float negc = -1.4426950408889634f / (l * l);   // -log2(e)/ls^2

    float qsx[4], qsy[4], qsz[4], Aq[4];
    #pragma unroll
    for (int j = 0; j < 4; j++) {
        const int q = qt * 32 + gr + 8 * j;
        const float* qp = qpos + (size_t)(b * Lc + q) * 3;
        const float x = qp[0], y = qp[1], z = qp[2];
        Aq[j]  = negc * (x * x + y * y + z * z);
        qsx[j] = -2.0f * negc * x;
        qsy[j] = -2.0f * negc * y;
        qsz[j] = -2.0f * negc * z;
    }

    const int nsteps = ((g_cnt[b] + 31) & ~31) >> 3;   // 8 keys per step

    float acc[2][4][4];
    #pragma unroll
    for (int m = 0; m < 2; m++)
        #pragma unroll
        for (int n = 0; n < 4; n++)
            #pragma unroll
            for (int r = 0; r < 4; r++) acc[m][n][r] = 0.0f;
    float denp[4] = {0.0f, 0.0f, 0.0f, 0.0f};

    const float4* kp4 = (const float4*)g_kpos4 + (size_t)b * Lc;
    const float2* vpw = (const float2*)g_vb +
                        (((size_t)b * 256) * 64 + h * 8 + nh * 4) * 32 + lane;

    // prologue: loads for step 0
    float4 ka = kp4[tc];
    float4 kc = kp4[tc + 4];
    float2 bf0 = vpw[0], bf1 = vpw[32], bf2 = vpw[64], bf3 = vpw[96];

    for (int s = 0; s < nsteps; s++) {
        // ---- issue next step's loads first (hidden under this step's math) ----
        const int sp = (s + 1 < nsteps) ? s + 1 : s;
        const float4 ka_n = kp4[sp * 8 + tc];
        const float4 kc_n = kp4[sp * 8 + tc + 4];
        const float2* vpn = vpw + (size_t)sp * 2048;
        const float2 bn0 = vpn[0], bn1 = vpn[32], bn2 = vpn[64], bn3 = vpn[96];

        // ---- exps from current kpos regs ----
        float ea[4], eb[4];
        #pragma unroll
        for (int j = 0; j < 4; j++) {
            float arg = fmaf(negc, ka.w, Aq[j]);
            arg = fmaf(qsx[j], ka.x, arg);
            arg = fmaf(qsy[j], ka.y, arg);
            arg = fmaf(qsz[j], ka.z, arg);
            ea[j] = ex2(arg);
            denp[j] += ea[j];
        }
        #pragma unroll
        for (int j = 0; j < 4; j++) {
            float arg = fmaf(negc, kc.w, Aq[j]);
            arg = fmaf(qsx[j], kc.x, arg);
            arg = fmaf(qsy[j], kc.y, arg);
            arg = fmaf(qsz[j], kc.z, arg);
            eb[j] = ex2(arg);
            denp[j] += eb[j];
        }

        unsigned a0[4], a1[4];
        a0[0] = __float_as_uint(to_tf32(ea[0]));
        a0[1] = __float_as_uint(to_tf32(ea[1]));
        a0[2] = __float_as_uint(to_tf32(eb[0]));
        a0[3] = __float_as_uint(to_tf32(eb[1]));
        a1[0] = __float_as_uint(to_tf32(ea[2]));
        a1[1] = __float_as_uint(to_tf32(ea[3]));
        a1[2] = __float_as_uint(to_tf32(eb[2]));
        a1[3] = __float_as_uint(to_tf32(eb[3]));

        // ---- mmas with current (already-resident) b-frags ----
        mma8(acc[0][0], a0, __float_as_uint(bf0.x), __float_as_uint(bf0.y));
        mma8(acc[1][0], a1, __float_as_uint(bf0.x), __float_as_uint(bf0.y));
        mma8(acc[0][1], a0, __float_as_uint(bf1.x), __float_as_uint(bf1.y));
        mma8(acc[1][1], a1, __float_as_uint(bf1.x), __float_as_uint(bf1.y));
        mma8(acc[0][2], a0, __float_as_uint(bf2.x), __float_as_uint(bf2.y));
        mma8(acc[1][2], a1, __float_as_uint(bf2.x), __float_as_uint(bf2.y));
        mma8(acc[0][3], a0, __float_as_uint(bf3.x), __float_as_uint(bf3.y));
        mma8(acc[1][3], a1, __float_as_uint(bf3.x), __float_as_uint(bf3.y));

        // ---- rotate ----
        ka = ka_n; kc = kc_n;
        bf0 = bn0; bf1 = bn1; bf2 = bn2; bf3 = bn3;
    }

    // den: reduce across the quad (lanes sharing gr, tc = 0..3)
    #pragma unroll
    for (int j = 0; j < 4; j++) {
        denp[j] += __shfl_xor_sync(0xFFFFFFFFu, denp[j], 1);
        denp[j] += __shfl_xor_sync(0xFFFFFFFFu, denp[j], 2);
    }

    // epilogue: normalize + write (4 n-tiles, n-half offset)
    #pragma unroll
    for (int m = 0; m < 2; m++) {
        const float i0 = 1.0f / (denp[2 * m] + 1e-5f);       // row gr + 16m
        const float i1 = 1.0f / (denp[2 * m + 1] + 1e-5f);   // row gr + 8 + 16m
        const int q0 = qt * 32 + m * 16 + gr;
        const size_t rb = (size_t)(b * Lc + q0) * HVc + h * 64 + nh * 32 + 2 * tc;
        #pragma unroll
        for (int n = 0; n < 4; n++) {
            *(float2*)&g_att[rb + n * 8] =
                make_float2(acc[m][n][0] * i0, acc[m][n][1] * i0);
            *(float2*)&g_att[rb + 8 * HVc + n * 8] =
                make_float2(acc[m][n][2] * i1, acc[m][n][3] * i1);
        }
    }
}

// ====== projection (unchanged): tf32 mma, 128x128 tile, W from g_wb ======
#define ASTRIDE 20   // 16 k + pad 4 -> bank(m-frag) = (20*gr+tc)%32, all distinct

__global__ __launch_bounds__(256, 2)
void proj_kernel(float* __restrict__ out)
{
    __shared__ float As[128 * ASTRIDE];   // [m][k] for current 16-k chunk

    const int tid = threadIdx.x;
    const int lane = tid & 31;
    const int warp = tid >> 5;
    const int gr = lane >> 2;
    const int tc = lane & 3;
    const int wm = warp & 1;       // 2 m-halves of 64
    const int wn = warp >> 1;      // 4 n-quarters of 32
    const int m0 = blockIdx.y * 128;

    const int row0 = tid >> 2;           // 0..63
    const int row1 = 64 + row0;
    const int cg   = (tid & 3) * 4;      // k sub-group within chunk

    float acc[4][4][4];
    #pragma unroll
    for (int mt = 0; mt < 4; mt++)
        #pragma unroll
        for (int nt = 0; nt < 4; nt++)
            #pragma unroll
            for (int r = 0; r < 4; r++) acc[mt][nt][r] = 0.0f;

    const float4* att4 = (const float4*)g_att;
    const float2* wb2 = (const float2*)g_wb;

    float4 r0 = att4[(size_t)(m0 + row0) * 128 + (cg >> 2)];
    float4 r1 = att4[(size_t)(m0 + row1) * 128 + (cg >> 2)];

    for (int k0 = 0; k0 < HVc; k0 += 16) {
        As[row0 * ASTRIDE + cg + 0] = to_tf32(r0.x);
        As[row0 * ASTRIDE + cg + 1] = to_tf32(r0.y);
        As[row0 * ASTRIDE + cg + 2] = to_tf32(r0.z);
        As[row0 * ASTRIDE + cg + 3] = to_tf32(r0.w);
        As[row1 * ASTRIDE + cg + 0] = to_tf32(r1.x);
        As[row1 * ASTRIDE + cg + 1] = to_tf32(r1.y);
        As[row1 * ASTRIDE + cg + 2] = to_tf32(r1.z);
        As[row1 * ASTRIDE + cg + 3] = to_tf32(r1.w);
        __syncthreads();

        if (k0 + 16 < HVc) {
            const int kn = (k0 + 16 + cg) >> 2;
            r0 = att4[(size_t)(m0 + row0) * 128 + kn];
            r1 = att4[(size_t)(m0 + row1) * 128 + kn];
        }

        #pragma unroll
        for (int kk = 0; kk < 2; kk++) {
            const int kc = kk * 8 + tc;
            unsigned a[4][4];
            #pragma unroll
            for (int mt = 0; mt < 4; mt++) {
                const int mr = wm * 64 + mt * 16 + gr;
                a[mt][0] = __float_as_uint(As[mr * ASTRIDE + kc]);
                a[mt][1] = __float_as_uint(As[(mr + 8) * ASTRIDE + kc]);
                a[mt][2] = __float_as_uint(As[mr * ASTRIDE + kc + 4]);
                a[mt][3] = __float_as_uint(As[(mr + 8) * ASTRIDE + kc + 4]);
            }
            const int kb = (k0 >> 3) + kk;
            const int nbase = blockIdx.x * 16 + wn * 4;
            #pragma unroll
            for (int nt = 0; nt < 4; nt++) {
                const float2 bb = wb2[(size_t)(kb * 64 + nbase + nt) * 32 + lane];
                const unsigned b0 = __float_as_uint(bb.x);
                const unsigned b1 = __float_as_uint(bb.y);
                #pragma unroll
                for (int mt = 0; mt < 4; mt++)
                    mma8(acc[mt][nt], a[mt], b0, b1);
            }
        }
        __syncthreads();
    }

    const int n0 = blockIdx.x * 128;
    #pragma unroll
    for (int mt = 0; mt < 4; mt++) {
        const int row = m0 + wm * 64 + mt * 16 + gr;
        #pragma unroll
        for (int nt = 0; nt < 4; nt++) {
            const int col = n0 + wn * 32 + nt * 8 + 2 * tc;
            *(float2*)&out[(size_t)row * HVc + col] =
                make_float2(acc[mt][nt][0], acc[mt][nt][1]);
            *(float2*)&out[(size_t)(row + 8) * HVc + col] =
                make_float2(acc[mt][nt][2], acc[mt][nt][3]);
        }
    }
}

extern "C" void kernel_launch(void* const* d_in, const int* in_sizes, int n_in,
                              void* d_out, int out_size)
{
    const float* qpos   = (const float*)d_in[0];
    const float* kpos   = (const float*)d_in[1];
    const float* values = (const float*)d_in[2];
    const int*   mask   = (const int*)  d_in[3];
    const float* ls     = (const float*)d_in[4];
    const float* w_out  = (const float*)d_in[5];
    float* out = (float*)d_out;

    compact_kernel<<<Bc, 32>>>(mask);
    gather_kernel<<<Bc * 32, NTHREADS>>>(kpos, values);
    prep_w<<<512, 256>>>(w_out);
    attend_kernel<<<1024, 128>>>(qpos, ls);
    proj_kernel<<<dim3(HVc / 128, (Bc * Lc) / 128), 256>>>(out);
}

// round 14
// speedup vs baseline: 1.0613x; 1.0613x over previous
#include <cuda_runtime.h>

#define Bc 4
#define Lc 2048
#define Hc 8
#define Vc 64
#define HVc 512
#define NTHREADS 256

__device__ __forceinline__ float to_tf32(float x) {
    float r; asm("cvt.rna.tf32.f32 %0, %1;" : "=f"(r) : "f"(x)); return r;
}
// D += A(m16k8,row) * B(k8n8,col), tf32
__device__ __forceinline__ void mma8(float* d, const unsigned* a,
                                     unsigned b0, unsigned b1) {
    asm("mma.sync.aligned.m16n8k8.row.col.f32.tf32.tf32.f32 "
        "{%0,%1,%2,%3}, {%4,%5,%6,%7}, {%8,%9}, {%0,%1,%2,%3};"
        : "+f"(d[0]), "+f"(d[1]), "+f"(d[2]), "+f"(d[3])
        : "r"(a[0]), "r"(a[1]), "r"(a[2]), "r"(a[3]), "r"(b0), "r"(b1));
}
__device__ __forceinline__ float ex2(float x) {
    float r; asm("ex2.approx.ftz.f32 %0, %1;" : "=f"(r) : "f"(x)); return r;
}

// ---- persistent device scratch ----
__device__ float g_att[Bc * Lc * HVc];          // normalized attended
__device__ float g_vb[Bc * 256 * 64 * 32 * 2];  // V in b-fragment order (tf32)
__device__ float g_wb[64 * 64 * 32 * 2];        // W in b-fragment order (tf32)
__device__ float g_kpos4[Bc * Lc * 4];          // compacted kpos (x,y,z,|k|^2), pad=1000
__device__ int   g_idx[Bc * Lc];
__device__ int   g_cnt[Bc];

// ================= compaction =================
__global__ void compact_kernel(const int* __restrict__ mask)
{
    const int b = blockIdx.x;
    const int lane = threadIdx.x;
    int cnt = 0;
    for (int k0 = 0; k0 < Lc; k0 += 32) {
        const int k = k0 + lane;
        const bool u = (mask[b * Lc + k] == 0);
        const unsigned bal = __ballot_sync(0xFFFFFFFFu, u);
        if (u) {
            const int pos = cnt + __popc(bal & ((1u << lane) - 1u));
            g_idx[b * Lc + pos] = k;
        }
        cnt += __popc(bal);
    }
    if (lane == 0) g_cnt[b] = cnt;
}

// ====== gather: values -> b-fragment layout (tf32); kpos4 with |k|^2 ======
__global__ void gather_kernel(const float* __restrict__ kpos,
                              const float* __restrict__ values)
{
    const int b  = blockIdx.x >> 5;
    const int j0 = (blockIdx.x & 31) * 64;
    const int tid = threadIdx.x;
    __shared__ int s_idx[64];
    __shared__ int s_n[2];

    if (tid == 0) { int c = g_cnt[b]; s_n[0] = c; s_n[1] = (c + 31) & ~31; }
    if (tid < 64 && j0 + tid < Lc) s_idx[tid] = g_idx[b * Lc + j0 + tid];
    __syncthreads();
    const int cnt = s_n[0];
    const int pad = s_n[1];
    const int jend = min(j0 + 64, pad);
    if (jend <= j0) return;
    const int nrows = jend - j0;

    const float4* v4 = (const float4*)values;
    for (int e = tid; e < nrows * 128; e += NTHREADS) {
        const int jl = e >> 7;
        const int c4 = e & 127;
        const int j  = j0 + jl;
        float4 v;
        if (j < cnt) v = v4[(size_t)(b * Lc + s_idx[jl]) * 128 + c4];
        else         v = make_float4(0.f, 0.f, 0.f, 0.f);
        v.x = to_tf32(v.x); v.y = to_tf32(v.y);
        v.z = to_tf32(v.z); v.w = to_tf32(v.w);
        const int ksg = j >> 3, kk = j & 7;
        const int tc = kk & 3, reg = kk >> 2;
        const float* pv = &v.x;
        #pragma unroll
        for (int t = 0; t < 4; t++) {
            const int c = c4 * 4 + t;
            const int h = c >> 6, n = (c >> 3) & 7, gr = c & 7;
            const size_t idx =
                ((((size_t)b * 256 + ksg) * 64 + h * 8 + n) * 32 + gr * 4 + tc) * 2 + reg;
            g_vb[idx] = pv[t];
        }
    }
    for (int jl = tid; jl < nrows; jl += NTHREADS) {
        const int j = j0 + jl;
        float x, y, z;
        if (j < cnt) {
            const float* p = kpos + (size_t)(b * Lc + s_idx[jl]) * 3;
            x = p[0]; y = p[1]; z = p[2];
        } else {
            x = y = z = 1000.0f;
        }
        const float k2 = x * x + y * y + z * z;
        ((float4*)g_kpos4)[(size_t)b * Lc + j] = make_float4(x, y, z, k2);
    }
}

// ====== W prepack: b-fragment order, tf32 ======
__global__ void prep_w(const float* __restrict__ W)
{
    const int p = blockIdx.x * 256 + threadIdx.x;   // float2 slot
    const int tc = p & 3;
    const int gr = (p >> 2) & 7;
    const int nb = (p >> 5) & 63;
    const int kb = p >> 11;
    const int row = nb * 8 + gr;
    const int col = kb * 8 + tc;
    g_wb[2 * p]     = to_tf32(W[row * HVc + col]);
    g_wb[2 * p + 1] = to_tf32(W[row * HVc + col + 4]);
}

// ====== attend: warp = (b, m16 query tile, head); N=64; reg pipeline ======
// acc 32 regs; no exp duplication; depth-1 prefetch of kpos4 + 8 b-frags.
__global__ __launch_bounds__(128, 4)
void attend_kernel(const float* __restrict__ qpos,
                   const float* __restrict__ ls)
{
    const int lane = threadIdx.x & 31;
    const int warp = threadIdx.x >> 5;
    const int gw = blockIdx.x * 4 + warp;   // 4096 warps total
    const int b  = gw >> 10;
    const int qt = (gw >> 3) & 127;         // 128 m16 tiles per batch
    const int h  = gw & 7;
    const int gr = lane >> 2;
    const int tc = lane & 3;

    const float l = ls[h];
    const float negc = -1.4426950408889634f / (l * l);   // -log2(e)/ls^2

    float qsx[2], qsy[2], qsz[2], Aq[2];
    #pragma unroll
    for (int j = 0; j < 2; j++) {
        const int q = qt * 16 + gr + 8 * j;
        const float* qp = qpos + (size_t)(b * Lc + q) * 3;
        const float x = qp[0], y = qp[1], z = qp[2];
        Aq[j]  = negc * (x * x + y * y + z * z);
        qsx[j] = -2.0f * negc * x;
        qsy[j] = -2.0f * negc * y;
        qsz[j] = -2.0f * negc * z;
    }

    const int nsteps = ((g_cnt[b] + 31) & ~31) >> 3;   // 8 keys per step

    float acc[8][4];
    #pragma unroll
    for (int n = 0; n < 8; n++)
        #pragma unroll
        for (int r = 0; r < 4; r++) acc[n][r] = 0.0f;
    float denp[2] = {0.0f, 0.0f};

    const float4* kp4 = (const float4*)g_kpos4 + (size_t)b * Lc;
    const float2* vpw = (const float2*)g_vb +
                        (((size_t)b * 256) * 64 + h * 8) * 32 + lane;

    // prologue: loads for step 0
    float4 ka = kp4[tc];
    float4 kc = kp4[tc + 4];
    float2 bf[8];
    #pragma unroll
    for (int n = 0; n < 8; n++) bf[n] = vpw[n * 32];

    for (int s = 0; s < nsteps; s++) {
        // ---- issue next step's loads (hidden under this step's math) ----
        const int sp = (s + 1 < nsteps) ? s + 1 : s;
        const float4 ka_n = kp4[sp * 8 + tc];
        const float4 kc_n = kp4[sp * 8 + tc + 4];
        const float2* vpn = vpw + (size_t)sp * 2048;
        float2 bn[8];
        #pragma unroll
        for (int n = 0; n < 8; n++) bn[n] = vpn[n * 32];

        // ---- exps: 4 per thread (rows gr, gr+8 x cols tc, tc+4) ----
        float ea[2], eb[2];
        #pragma unroll
        for (int j = 0; j < 2; j++) {
            float arg = fmaf(negc, ka.w, Aq[j]);
            arg = fmaf(qsx[j], ka.x, arg);
            arg = fmaf(qsy[j], ka.y, arg);
            arg = fmaf(qsz[j], ka.z, arg);
            ea[j] = ex2(arg);
            denp[j] += ea[j];
        }
        #pragma unroll
        for (int j = 0; j < 2; j++) {
            float arg = fmaf(negc, kc.w, Aq[j]);
            arg = fmaf(qsx[j], kc.x, arg);
            arg = fmaf(qsy[j], kc.y, arg);
            arg = fmaf(qsz[j], kc.z, arg);
            eb[j] = ex2(arg);
            denp[j] += eb[j];
        }

        unsigned a[4];
        a[0] = __float_as_uint(to_tf32(ea[0]));
        a[1] = __float_as_uint(to_tf32(ea[1]));
        a[2] = __float_as_uint(to_tf32(eb[0]));
        a[3] = __float_as_uint(to_tf32(eb[1]));

        // ---- 8 mmas with resident b-frags ----
        #pragma unroll
        for (int n = 0; n < 8; n++)
            mma8(acc[n], a, __float_as_uint(bf[n].x), __float_as_uint(bf[n].y));

        // ---- rotate ----
        ka = ka_n; kc = kc_n;
        #pragma unroll
        for (int n = 0; n < 8; n++) bf[n] = bn[n];
    }

    // den: reduce across the quad (lanes sharing gr, tc = 0..3)
    #pragma unroll
    for (int j = 0; j < 2; j++) {
        denp[j] += __shfl_xor_sync(0xFFFFFFFFu, denp[j], 1);
        denp[j] += __shfl_xor_sync(0xFFFFFFFFu, denp[j], 2);
    }

    // epilogue: normalize + write rows gr, gr+8
    const float i0 = 1.0f / (denp[0] + 1e-5f);
    const float i1 = 1.0f / (denp[1] + 1e-5f);
    const int q0 = qt * 16 + gr;
    const size_t rb = (size_t)(b * Lc + q0) * HVc + h * 64 + 2 * tc;
    #pragma unroll
    for (int n = 0; n < 8; n++) {
        *(float2*)&g_att[rb + n * 8] =
            make_float2(acc[n][0] * i0, acc[n][1] * i0);
        *(float2*)&g_att[rb + 8 * HVc + n * 8] =
            make_float2(acc[n][2] * i1, acc[n][3] * i1);
    }
}

// ====== projection (unchanged): tf32 mma, 128x128 tile, W from g_wb ======
#define ASTRIDE 20   // 16 k + pad 4 -> bank(m-frag) = (20*gr+tc)%32, all distinct

__global__ __launch_bounds__(256, 2)
void proj_kernel(float* __restrict__ out)
{
    __shared__ float As[128 * ASTRIDE];   // [m][k] for current 16-k chunk

    const int tid = threadIdx.x;
    const int lane = tid & 31;
    const int warp = tid >> 5;
    const int gr = lane >> 2;
    const int tc = lane & 3;
    const int wm = warp & 1;       // 2 m-halves of 64
    const int wn = warp >> 1;      // 4 n-quarters of 32
    const int m0 = blockIdx.y * 128;

    const int row0 = tid >> 2;           // 0..63
    const int row1 = 64 + row0;
    const int cg   = (tid & 3) * 4;      // k sub-group within chunk

    float acc[4][4][4];
    #pragma unroll
    for (int mt = 0; mt < 4; mt++)
        #pragma unroll
        for (int nt = 0; nt < 4; nt++)
            #pragma unroll
            for (int r = 0; r < 4; r++) acc[mt][nt][r] = 0.0f;

    const float4* att4 = (const float4*)g_att;
    const float2* wb2 = (const float2*)g_wb;

    float4 r0 = att4[(size_t)(m0 + row0) * 128 + (cg >> 2)];
    float4 r1 = att4[(size_t)(m0 + row1) * 128 + (cg >> 2)];

    for (int k0 = 0; k0 < HVc; k0 += 16) {
        As[row0 * ASTRIDE + cg + 0] = to_tf32(r0.x);
        As[row0 * ASTRIDE + cg + 1] = to_tf32(r0.y);
        As[row0 * ASTRIDE + cg + 2] = to_tf32(r0.z);
        As[row0 * ASTRIDE + cg + 3] = to_tf32(r0.w);
        As[row1 * ASTRIDE + cg + 0] = to_tf32(r1.x);
        As[row1 * ASTRIDE + cg + 1] = to_tf32(r1.y);
        As[row1 * ASTRIDE + cg + 2] = to_tf32(r1.z);
        As[row1 * ASTRIDE + cg + 3] = to_tf32(r1.w);
        __syncthreads();

        if (k0 + 16 < HVc) {
            const int kn = (k0 + 16 + cg) >> 2;
            r0 = att4[(size_t)(m0 + row0) * 128 + kn];
            r1 = att4[(size_t)(m0 + row1) * 128 + kn];
        }

        #pragma unroll
        for (int kk = 0; kk < 2; kk++) {
            const int kc = kk * 8 + tc;
            unsigned a[4][4];
            #pragma unroll
            for (int mt = 0; mt < 4; mt++) {
                const int mr = wm * 64 + mt * 16 + gr;
                a[mt][0] = __float_as_uint(As[mr * ASTRIDE + kc]);
                a[mt][1] = __float_as_uint(As[(mr + 8) * ASTRIDE + kc]);
                a[mt][2] = __float_as_uint(As[mr * ASTRIDE + kc + 4]);
                a[mt][3] = __float_as_uint(As[(mr + 8) * ASTRIDE + kc + 4]);
            }
            const int kb = (k0 >> 3) + kk;
            const int nbase = blockIdx.x * 16 + wn * 4;
            #pragma unroll
            for (int nt = 0; nt < 4; nt++) {
                const float2 bb = wb2[(size_t)(kb * 64 + nbase + nt) * 32 + lane];
                const unsigned b0 = __float_as_uint(bb.x);
                const unsigned b1 = __float_as_uint(bb.y);
                #pragma unroll
                for (int mt = 0; mt < 4; mt++)
                    mma8(acc[mt][nt], a[mt], b0, b1);
            }
        }
        __syncthreads();
    }

    const int n0 = blockIdx.x * 128;
    #pragma unroll
    for (int mt = 0; mt < 4; mt++) {
        const int row = m0 + wm * 64 + mt * 16 + gr;
        #pragma unroll
        for (int nt = 0; nt < 4; nt++) {
            const int col = n0 + wn * 32 + nt * 8 + 2 * tc;
            *(float2*)&out[(size_t)row * HVc + col] =
                make_float2(acc[mt][nt][0], acc[mt][nt][1]);
            *(float2*)&out[(size_t)(row + 8) * HVc + col] =
                make_float2(acc[mt][nt][2], acc[mt][nt][3]);
        }
    }
}

extern "C" void kernel_launch(void* const* d_in, const int* in_sizes, int n_in,
                              void* d_out, int out_size)
{
    const float* qpos   = (const float*)d_in[0];
    const float* kpos   = (const float*)d_in[1];
    const float* values = (const float*)d_in[2];
    const int*   mask   = (const int*)  d_in[3];
    const float* ls     = (const float*)d_in[4];
    const float* w_out  = (const float*)d_in[5];
    float* out = (float*)d_out;

    compact_kernel<<<Bc, 32>>>(mask);
    gather_kernel<<<Bc * 32, NTHREADS>>>(kpos, values);
    prep_w<<<512, 256>>>(w_out);
    attend_kernel<<<1024, 128>>>(qpos, ls);
    proj_kernel<<<dim3(HVc / 128, (Bc * Lc) / 128), 256>>>(out);
}

// round 15
// speedup vs baseline: 1.0623x; 1.0009x over previous
#include <cuda_runtime.h>

#define Bc 4
#define Lc 2048
#define Hc 8
#define Vc 64
#define HVc 512
#define NTHREADS 256

__device__ __forceinline__ float to_tf32(float x) {
    float r; asm("cvt.rna.tf32.f32 %0, %1;" : "=f"(r) : "f"(x)); return r;
}
// D += A(m16k8,row) * B(k8n8,col), tf32
__device__ __forceinline__ void mma8(float* d, const unsigned* a,
                                     unsigned b0, unsigned b1) {
    asm("mma.sync.aligned.m16n8k8.row.col.f32.tf32.tf32.f32 "
        "{%0,%1,%2,%3}, {%4,%5,%6,%7}, {%8,%9}, {%0,%1,%2,%3};"
        : "+f"(d[0]), "+f"(d[1]), "+f"(d[2]), "+f"(d[3])
        : "r"(a[0]), "r"(a[1]), "r"(a[2]), "r"(a[3]), "r"(b0), "r"(b1));
}
__device__ __forceinline__ float ex2(float x) {
    float r; asm("ex2.approx.ftz.f32 %0, %1;" : "=f"(r) : "f"(x)); return r;
}

// ---- persistent device scratch ----
__device__ float g_att[Bc * Lc * HVc];          // normalized attended
__device__ float g_vb[Bc * 256 * 64 * 32 * 2];  // V b-frags, n-PAIRED float4 layout
__device__ float g_wb[64 * 64 * 32 * 2];        // W in b-fragment order (tf32)
__device__ float g_kpos4[Bc * Lc * 4];          // compacted kpos (x,y,z,|k|^2), pad=1000
__device__ int   g_idx[Bc * Lc];
__device__ int   g_cnt[Bc];

// ================= compaction =================
__global__ void compact_kernel(const int* __restrict__ mask)
{
    const int b = blockIdx.x;
    const int lane = threadIdx.x;
    int cnt = 0;
    for (int k0 = 0; k0 < Lc; k0 += 32) {
        const int k = k0 + lane;
        const bool u = (mask[b * Lc + k] == 0);
        const unsigned bal = __ballot_sync(0xFFFFFFFFu, u);
        if (u) {
            const int pos = cnt + __popc(bal & ((1u << lane) - 1u));
            g_idx[b * Lc + pos] = k;
        }
        cnt += __popc(bal);
    }
    if (lane == 0) g_cnt[b] = cnt;
}

// ====== gather: values -> PAIRED b-fragment layout (tf32); kpos4 ======
// scalar idx for V[j][c], c = h*64 + n*8 + gr, j -> (ksg=j>>3, kk=j&7, tc=kk&3, reg=kk>>2):
//   np = n>>1, nl = n&1
//   idx = ((((b*256+ksg)*32 + h*4 + np)*32 + gr*4 + tc)*4 + nl*2 + reg
__global__ void gather_kernel(const float* __restrict__ kpos,
                              const float* __restrict__ values)
{
    const int b  = blockIdx.x >> 5;
    const int j0 = (blockIdx.x & 31) * 64;
    const int tid = threadIdx.x;
    __shared__ int s_idx[64];
    __shared__ int s_n[2];

    if (tid == 0) { int c = g_cnt[b]; s_n[0] = c; s_n[1] = (c + 31) & ~31; }
    if (tid < 64 && j0 + tid < Lc) s_idx[tid] = g_idx[b * Lc + j0 + tid];
    __syncthreads();
    const int cnt = s_n[0];
    const int pad = s_n[1];
    const int jend = min(j0 + 64, pad);
    if (jend <= j0) return;
    const int nrows = jend - j0;

    const float4* v4 = (const float4*)values;
    for (int e = tid; e < nrows * 128; e += NTHREADS) {
        const int jl = e >> 7;
        const int c4 = e & 127;
        const int j  = j0 + jl;
        float4 v;
        if (j < cnt) v = v4[(size_t)(b * Lc + s_idx[jl]) * 128 + c4];
        else         v = make_float4(0.f, 0.f, 0.f, 0.f);
        v.x = to_tf32(v.x); v.y = to_tf32(v.y);
        v.z = to_tf32(v.z); v.w = to_tf32(v.w);
        const int ksg = j >> 3, kk = j & 7;
        const int tc = kk & 3, reg = kk >> 2;
        const float* pv = &v.x;
        #pragma unroll
        for (int t = 0; t < 4; t++) {
            const int c = c4 * 4 + t;
            const int h = c >> 6, n = (c >> 3) & 7, gr = c & 7;
            const size_t idx =
                (((((size_t)b * 256 + ksg) * 32 + h * 4 + (n >> 1)) * 32
                  + gr * 4 + tc) * 4) + (n & 1) * 2 + reg;
            g_vb[idx] = pv[t];
        }
    }
    for (int jl = tid; jl < nrows; jl += NTHREADS) {
        const int j = j0 + jl;
        float x, y, z;
        if (j < cnt) {
            const float* p = kpos + (size_t)(b * Lc + s_idx[jl]) * 3;
            x = p[0]; y = p[1]; z = p[2];
        } else {
            x = y = z = 1000.0f;
        }
        const float k2 = x * x + y * y + z * z;
        ((float4*)g_kpos4)[(size_t)b * Lc + j] = make_float4(x, y, z, k2);
    }
}

// ====== W prepack: b-fragment order, tf32 (float2 layout, proj-only) ======
__global__ void prep_w(const float* __restrict__ W)
{
    const int p = blockIdx.x * 256 + threadIdx.x;   // float2 slot
    const int tc = p & 3;
    const int gr = (p >> 2) & 7;
    const int nb = (p >> 5) & 63;
    const int kb = p >> 11;
    const int row = nb * 8 + gr;
    const int col = kb * 8 + tc;
    g_wb[2 * p]     = to_tf32(W[row * HVc + col]);
    g_wb[2 * p + 1] = to_tf32(W[row * HVc + col + 4]);
}

// ====== attend: warp = (b, m16 query tile, head); N=64; occ-5 pipeline ======
// acc 32 regs; b-frag prefetch only (kpos unprefetched); float4-paired V loads.
__global__ __launch_bounds__(128, 5)
void attend_kernel(const float* __restrict__ qpos,
                   const float* __restrict__ ls)
{
    const int lane = threadIdx.x & 31;
    const int warp = threadIdx.x >> 5;
    const int gw = blockIdx.x * 4 + warp;   // 4096 warps total
    const int b  = gw >> 10;
    const int qt = (gw >> 3) & 127;         // 128 m16 tiles per batch
    const int h  = gw & 7;
    const int gr = lane >> 2;
    const int tc = lane & 3;

    const float l = ls[h];
    const float negc = -1.4426950408889634f / (l * l);   // -log2(e)/ls^2

    float qsx[2], qsy[2], qsz[2], Aq[2];
    #pragma unroll
    for (int j = 0; j < 2; j++) {
        const int q = qt * 16 + gr + 8 * j;
        const float* qp = qpos + (size_t)(b * Lc + q) * 3;
        const float x = qp[0], y = qp[1], z = qp[2];
        Aq[j]  = negc * (x * x + y * y + z * z);
        qsx[j] = -2.0f * negc * x;
        qsy[j] = -2.0f * negc * y;
        qsz[j] = -2.0f * negc * z;
    }

    const int nsteps = ((g_cnt[b] + 31) & ~31) >> 3;   // 8 keys per step

    float acc[8][4];
    #pragma unroll
    for (int n = 0; n < 8; n++)
        #pragma unroll
        for (int r = 0; r < 4; r++) acc[n][r] = 0.0f;
    float denp[2] = {0.0f, 0.0f};

    const float4* kp4 = (const float4*)g_kpos4 + (size_t)b * Lc;
    const float4* vpw = (const float4*)g_vb +
                        (((size_t)b * 256) * 32 + h * 4) * 32 + lane;

    // prologue: b-frags for step 0
    float4 bf[4];
    #pragma unroll
    for (int p = 0; p < 4; p++) bf[p] = vpw[p * 32];

    #pragma unroll 2
    for (int s = 0; s < nsteps; s++) {
        // ---- next step's b-frags issued first (hidden under this step) ----
        const int sp = (s + 1 < nsteps) ? s + 1 : s;
        const float4* vpn = vpw + sp * 1024;
        float4 bn[4];
        #pragma unroll
        for (int p = 0; p < 4; p++) bn[p] = vpn[p * 32];

        // ---- kpos (1-line broadcast, L2-hot) + exps ----
        const float4 ka = kp4[s * 8 + tc];
        const float4 kc = kp4[s * 8 + tc + 4];

        float ea[2], eb[2];
        #pragma unroll
        for (int j = 0; j < 2; j++) {
            float arg = fmaf(negc, ka.w, Aq[j]);
            arg = fmaf(qsx[j], ka.x, arg);
            arg = fmaf(qsy[j], ka.y, arg);
            arg = fmaf(qsz[j], ka.z, arg);
            ea[j] = ex2(arg);
            denp[j] += ea[j];
        }
        #pragma unroll
        for (int j = 0; j < 2; j++) {
            float arg = fmaf(negc, kc.w, Aq[j]);
            arg = fmaf(qsx[j], kc.x, arg);
            arg = fmaf(qsy[j], kc.y, arg);
            arg = fmaf(qsz[j], kc.z, arg);
            eb[j] = ex2(arg);
            denp[j] += eb[j];
        }

        unsigned a[4];
        a[0] = __float_as_uint(to_tf32(ea[0]));
        a[1] = __float_as_uint(to_tf32(ea[1]));
        a[2] = __float_as_uint(to_tf32(eb[0]));
        a[3] = __float_as_uint(to_tf32(eb[1]));

        // ---- 8 mmas with resident paired b-frags ----
        #pragma unroll
        for (int p = 0; p < 4; p++) {
            mma8(acc[2 * p],     a, __float_as_uint(bf[p].x), __float_as_uint(bf[p].y));
            mma8(acc[2 * p + 1], a, __float_as_uint(bf[p].z), __float_as_uint(bf[p].w));
        }

        // ---- rotate ----
        #pragma unroll
        for (int p = 0; p < 4; p++) bf[p] = bn[p];
    }

    // den: reduce across the quad (lanes sharing gr, tc = 0..3)
    #pragma unroll
    for (int j = 0; j < 2; j++) {
        denp[j] += __shfl_xor_sync(0xFFFFFFFFu, denp[j], 1);
        denp[j] += __shfl_xor_sync(0xFFFFFFFFu, denp[j], 2);
    }

    // epilogue: normalize + write rows gr, gr+8
    const float i0 = 1.0f / (denp[0] + 1e-5f);
    const float i1 = 1.0f / (denp[1] + 1e-5f);
    const int q0 = qt * 16 + gr;
    const size_t rb = (size_t)(b * Lc + q0) * HVc + h * 64 + 2 * tc;
    #pragma unroll
    for (int n = 0; n < 8; n++) {
        *(float2*)&g_att[rb + n * 8] =
            make_float2(acc[n][0] * i0, acc[n][1] * i0);
        *(float2*)&g_att[rb + 8 * HVc + n * 8] =
            make_float2(acc[n][2] * i1, acc[n][3] * i1);
    }
}

// ====== projection (unchanged): tf32 mma, 128x128 tile, W from g_wb ======
#define ASTRIDE 20   // 16 k + pad 4 -> bank(m-frag) = (20*gr+tc)%32, all distinct

__global__ __launch_bounds__(256, 2)
void proj_kernel(float* __restrict__ out)
{
    __shared__ float As[128 * ASTRIDE];   // [m][k] for current 16-k chunk

    const int tid = threadIdx.x;
    const int lane = tid & 31;
    const int warp = tid >> 5;
    const int gr = lane >> 2;
    const int tc = lane & 3;
    const int wm = warp & 1;       // 2 m-halves of 64
    const int wn = warp >> 1;      // 4 n-quarters of 32
    const int m0 = blockIdx.y * 128;

    const int row0 = tid >> 2;           // 0..63
    const int row1 = 64 + row0;
    const int cg   = (tid & 3) * 4;      // k sub-group within chunk

    float acc[4][4][4];
    #pragma unroll
    for (int mt = 0; mt < 4; mt++)
        #pragma unroll
        for (int nt = 0; nt < 4; nt++)
            #pragma unroll
            for (int r = 0; r < 4; r++) acc[mt][nt][r] = 0.0f;

    const float4* att4 = (const float4*)g_att;
    const float2* wb2 = (const float2*)g_wb;

    float4 r0 = att4[(size_t)(m0 + row0) * 128 + (cg >> 2)];
    float4 r1 = att4[(size_t)(m0 + row1) * 128 + (cg >> 2)];

    for (int k0 = 0; k0 < HVc; k0 += 16) {
        As[row0 * ASTRIDE + cg + 0] = to_tf32(r0.x);
        As[row0 * ASTRIDE + cg + 1] = to_tf32(r0.y);
        As[row0 * ASTRIDE + cg + 2] = to_tf32(r0.z);
        As[row0 * ASTRIDE + cg + 3] = to_tf32(r0.w);
        As[row1 * ASTRIDE + cg + 0] = to_tf32(r1.x);
        As[row1 * ASTRIDE + cg + 1] = to_tf32(r1.y);
        As[row1 * ASTRIDE + cg + 2] = to_tf32(r1.z);
        As[row1 * ASTRIDE + cg + 3] = to_tf32(r1.w);
        __syncthreads();

        if (k0 + 16 < HVc) {
            const int kn = (k0 + 16 + cg) >> 2;
            r0 = att4[(size_t)(m0 + row0) * 128 + kn];
            r1 = att4[(size_t)(m0 + row1) * 128 + kn];
        }

        #pragma unroll
        for (int kk = 0; kk < 2; kk++) {
            const int kc = kk * 8 + tc;
            unsigned a[4][4];
            #pragma unroll
            for (int mt = 0; mt < 4; mt++) {
                const int mr = wm * 64 + mt * 16 + gr;
                a[mt][0] = __float_as_uint(As[mr * ASTRIDE + kc]);
                a[mt][1] = __float_as_uint(As[(mr + 8) * ASTRIDE + kc]);
                a[mt][2] = __float_as_uint(As[mr * ASTRIDE + kc + 4]);
                a[mt][3] = __float_as_uint(As[(mr + 8) * ASTRIDE + kc + 4]);
            }
            const int kb = (k0 >> 3) + kk;
            const int nbase = blockIdx.x * 16 + wn * 4;
            #pragma unroll
            for (int nt = 0; nt < 4; nt++) {
                const float2 bb = wb2[(size_t)(kb * 64 + nbase + nt) * 32 + lane];
                const unsigned b0 = __float_as_uint(bb.x);
                const unsigned b1 = __float_as_uint(bb.y);
                #pragma unroll
                for (int mt = 0; mt < 4; mt++)
                    mma8(acc[mt][nt], a[mt], b0, b1);
            }
        }
        __syncthreads();
    }

    const int n0 = blockIdx.x * 128;
    #pragma unroll
    for (int mt = 0; mt < 4; mt++) {
        const int row = m0 + wm * 64 + mt * 16 + gr;
        #pragma unroll
        for (int nt = 0; nt < 4; nt++) {
            const int col = n0 + wn * 32 + nt * 8 + 2 * tc;
            *(float2*)&out[(size_t)row * HVc + col] =
                make_float2(acc[mt][nt][0], acc[mt][nt][1]);
            *(float2*)&out[(size_t)(row + 8) * HVc + col] =
                make_float2(acc[mt][nt][2], acc[mt][nt][3]);
        }
    }
}

extern "C" void kernel_launch(void* const* d_in, const int* in_sizes, int n_in,
                              void* d_out, int out_size)
{
    const float* qpos   = (const float*)d_in[0];
    const float* kpos   = (const float*)d_in[1];
    const float* values = (const float*)d_in[2];
    const int*   mask   = (const int*)  d_in[3];
    const float* ls     = (const float*)d_in[4];
    const float* w_out  = (const float*)d_in[5];
    float* out = (float*)d_out;

    compact_kernel<<<Bc, 32>>>(mask);
    gather_kernel<<<Bc * 32, NTHREADS>>>(kpos, values);
    prep_w<<<512, 256>>>(w_out);
    attend_kernel<<<1024, 128>>>(qpos, ls);
    proj_kernel<<<dim3(HVc / 128, (Bc * Lc) / 128), 256>>>(out);
}